// round 9
// baseline (speedup 1.0000x reference)
#include <cuda_runtime.h>
#include <cuda_bf16.h>
#include <cstdint>

// LearnableTopP: per row of 1024 fp32 softmax probs:
//   descending stable sort (ties -> smaller original index first),
//   inclusive cumsum, mask = cumsum <= sigmoid(threshold[s % 16]),
//   padded_idx = mask ? sorted_index : -1, counts = popcount(mask).
// Outputs as FLOAT32: [ padded_idx (rows*1024) | counts (rows) ].
//
// One warp per row; 32 elements per lane, kept as TWO float registers each
// (struct-of-arrays, never packed):
//   hi[r] = value                (softmax output: finite, >= 0, no NaN ->
//                                 float '>' == unsigned compare of bit patterns)
//   lo[r] = (float)(1023 - idx)  (tiebreak: larger lo == smaller original idx,
//                                 exactly representable)
// Comparator predicate: q = (ah > bh) | (ah == bh & al > bl)
//   -> FSETP.GT.OR / FSETP.EQ.AND / FSETP.GT chain on the FP pipe,
//      relieving the saturated ALU pipe (was 96% busy; fma pipe 1.7%).
// Selects are float selp (mux; bit-exact either way).
// Sort order identical bit-for-bit to the packed-u64 version.

using u32 = unsigned int;

// full compare-exchange: lo/hi pair at (Ah,Al) keeps the larger key iff dir.
static __device__ __forceinline__ void cas2(float &Ah, float &Al,
                                            float &Bh, float &Bl, bool dir) {
    float ah = Ah, al = Al, bh = Bh, bl = Bl;
    bool gt = (ah > bh) | ((ah == bh) & (al > bl));  // a > b (total order)
    bool q  = (gt == dir);                            // q: a stays in slot A
    Ah = q ? ah : bh;  Al = q ? al : bl;
    Bh = q ? bh : ah;  Bl = q ? bl : al;
}

__global__ void __launch_bounds__(256) topp_sort_kernel(
    const float* __restrict__ atn,
    const float* __restrict__ thresholds,
    float* __restrict__ out_idx,
    float* __restrict__ out_counts)
{
    const int warp = threadIdx.x >> 5;
    const int lane = threadIdx.x & 31;
    const int row  = blockIdx.x * 8 + warp;   // 65536 rows, 8 warps/CTA

    const float* rowp = atn + (size_t)row * 1024;

    // --- load 32 contiguous elements per lane (positions lane*32 + r) ---
    float hi[32], lo[32];
    const float4* rowp4 = reinterpret_cast<const float4*>(rowp);
    const float base_f = (float)(1023 - (lane << 5));   // 1023 - lane*32
#pragma unroll
    for (int q = 0; q < 8; ++q) {
        float4 f = rowp4[lane * 8 + q];
        hi[q * 4 + 0] = f.x;  lo[q * 4 + 0] = base_f - (float)(q * 4 + 0);
        hi[q * 4 + 1] = f.y;  lo[q * 4 + 1] = base_f - (float)(q * 4 + 1);
        hi[q * 4 + 2] = f.z;  lo[q * 4 + 2] = base_f - (float)(q * 4 + 2);
        hi[q * 4 + 3] = f.w;  lo[q * 4 + 3] = base_f - (float)(q * 4 + 3);
    }

    // --- bitonic sort, descending over global positions i = lane*32 + r ---
#pragma unroll
    for (int k = 2; k <= 1024; k <<= 1) {
#pragma unroll
        for (int j = k >> 1; j > 0; j >>= 1) {
            if (j >= 32) {
                // cross-lane phase: partner lane = lane ^ (j>>5), same r slot
                const int jl = j >> 5;
                const bool isLower = ((lane & jl) == 0);
                const bool descBlk = ((lane & (k >> 5)) == 0);   // (i & k) == 0
                const bool keepMax = (descBlk == isLower);
#pragma unroll
                for (int r = 0; r < 32; ++r) {
                    float ah = hi[r], al = lo[r];
                    float bh = __shfl_xor_sync(0xffffffffu, ah, jl);
                    float bl = __shfl_xor_sync(0xffffffffu, al, jl);
                    bool gt = (ah > bh) | ((ah == bh) & (al > bl));
                    bool q  = (gt == keepMax);
                    hi[r] = q ? ah : bh;
                    lo[r] = q ? al : bl;
                }
            } else {
                // intra-lane phase: partner register r ^ j
#pragma unroll
                for (int r = 0; r < 32; ++r) {
                    if ((r & j) == 0) {
                        const int p = r, s = r | j;
                        bool descBlk;
                        if (k >= 32) descBlk = ((lane & (k >> 5)) == 0); // runtime (lane bits)
                        else         descBlk = ((p & k) == 0);           // compile-time
                        cas2(hi[p], lo[p], hi[s], lo[s], descBlk);
                    }
                }
            }
        }
    }

    // --- threshold: row (h*S + s) uses threshold[s % 16] == row % 16 ---
    float t   = thresholds[row & 15];
    float thr = 1.0f / (1.0f + expf(-t));

    // --- cumsum: lane-local total, warp exclusive scan, streamed prefix ---
    float tot = 0.0f;
#pragma unroll
    for (int r = 0; r < 32; ++r)
        tot += hi[r];

    float scan = tot;
#pragma unroll
    for (int d = 1; d < 32; d <<= 1) {
        float n = __shfl_up_sync(0xffffffffu, scan, d);
        if (lane >= d) scan += n;
    }
    float run = scan - tot;   // exclusive offset for this lane

    // --- emit padded indices (as float) + count ---
    float4* orow = reinterpret_cast<float4*>(out_idx + (size_t)row * 1024);
    float fcnt = 0.0f;
    float ov[4];
#pragma unroll
    for (int r = 0; r < 32; ++r) {
        run += hi[r];                       // inclusive cumsum
        bool sel = (run <= thr);
        float id = 1023.0f - lo[r];         // original index, exact
        ov[r & 3] = sel ? id : -1.0f;
        fcnt += sel ? 1.0f : 0.0f;
        if ((r & 3) == 3)
            orow[lane * 8 + (r >> 2)] = make_float4(ov[0], ov[1], ov[2], ov[3]);
    }

    if (out_counts) {
#pragma unroll
        for (int d = 16; d > 0; d >>= 1)
            fcnt += __shfl_xor_sync(0xffffffffu, fcnt, d);
        if (lane == 0) out_counts[row] = fcnt;
    }
}

extern "C" void kernel_launch(void* const* d_in, const int* in_sizes, int n_in,
                              void* d_out, int out_size)
{
    const float* atn = (const float*)d_in[0];
    const float* thr = (const float*)d_in[1];
    (void)n_in;

    const int S    = 1024;
    const int rows = in_sizes[0] / S;                 // 65536
    long long padded = (long long)rows * S;           // 67,108,864

    float* out    = (float*)d_out;
    float* counts = ((long long)out_size >= padded + rows) ? (out + padded) : nullptr;

    dim3 block(256);                                  // 8 warps = 8 rows per CTA
    dim3 grid(rows / 8);
    topp_sort_kernel<<<grid, block>>>(atn, thr, out, counts);
}

// round 10
// speedup vs baseline: 1.0064x; 1.0064x over previous
#include <cuda_runtime.h>
#include <cuda_bf16.h>
#include <cstdint>

// LearnableTopP: per row of 1024 fp32 softmax probs:
//   descending stable sort (ties -> smaller original index first),
//   inclusive cumsum, mask = cumsum <= sigmoid(threshold[s % 16]),
//   padded_idx = mask ? sorted_index : -1, counts = popcount(mask).
// Outputs as FLOAT32: [ padded_idx (rows*1024) | counts (rows) ].
//
// One warp per row; 32 packed u64 keys per lane:
//   key = ((u64)valbits << 32) | (1023 - idx)
// hi word = raw fp32 value bits (values are NORMAL positive floats: min
// softmax prob ~1e-8 >> denormal range, so FTZ/fast-math can't corrupt them);
// lo word = tiebreak index. 64-bit unsigned compare == (value desc, idx asc).
//
// ALU-pipe relief: the kernel is ALU-bound (96% pipe, fma idle). The hi-word
// routing of each intra-lane compare-exchange is done ARITHMETICALLY on the
// FMA pipe:  pf = q?1:0;  hiA = fmaf(pf, ah, (1-pf)*bh)  (exact: every
// product is ah, bh or +-0; x+0 exact for these operands).
// Lo-word routing stays on integer SEL.  Compare stays the 2-op ISETP/.EX
// chain (hi/lo extraction from the u64 is free register-pair selection).

using u64 = unsigned long long;
using u32 = unsigned int;

// intra-lane compare-exchange, hi words routed via FMA pipe.
static __device__ __forceinline__ void cas_fma(u64 &A, u64 &B, bool dir) {
    u64 a = A, b = B;
    bool q = (a > b) == dir;                    // 2x ISETP (ALU), dir folded
    float pf = q ? 1.0f : 0.0f;                 // SEL   (ALU)
    float qf = 1.0f - pf;                       // FADD  (FMA pipe)
    float ah = __uint_as_float((u32)(a >> 32)); // free (register half)
    float bh = __uint_as_float((u32)(b >> 32));
    u32  al = (u32)a, bl = (u32)b;              // free
    float Ah = fmaf(pf, ah, qf * bh);           // FMUL+FFMA (FMA pipe)
    float Bh = fmaf(pf, bh, qf * ah);           // FMUL+FFMA (FMA pipe)
    u32  Al = q ? al : bl;                      // SEL (ALU)
    u32  Bl = q ? bl : al;                      // SEL (ALU)
    A = ((u64)__float_as_uint(Ah) << 32) | Al;  // free (register pair)
    B = ((u64)__float_as_uint(Bh) << 32) | Bl;  // free
}

__global__ void __launch_bounds__(256) topp_sort_kernel(
    const float* __restrict__ atn,
    const float* __restrict__ thresholds,
    float* __restrict__ out_idx,
    float* __restrict__ out_counts)
{
    const int warp = threadIdx.x >> 5;
    const int lane = threadIdx.x & 31;
    const int row  = blockIdx.x * 8 + warp;   // 65536 rows, 8 warps/CTA

    const float* rowp = atn + (size_t)row * 1024;

    // --- load 32 contiguous elements per lane, pack keys (hi=valbits, lo=1023-idx) ---
    u64 key[32];
    const float4* rowp4 = reinterpret_cast<const float4*>(rowp);
#pragma unroll
    for (int q = 0; q < 8; ++q) {
        float4 f = rowp4[lane * 8 + q];
        int base = (lane << 5) + (q << 2);
        key[q * 4 + 0] = ((u64)__float_as_uint(f.x) << 32) | (u32)(1023 - (base + 0));
        key[q * 4 + 1] = ((u64)__float_as_uint(f.y) << 32) | (u32)(1023 - (base + 1));
        key[q * 4 + 2] = ((u64)__float_as_uint(f.z) << 32) | (u32)(1023 - (base + 2));
        key[q * 4 + 3] = ((u64)__float_as_uint(f.w) << 32) | (u32)(1023 - (base + 3));
    }

    // --- bitonic sort, descending over global positions i = lane*32 + r ---
#pragma unroll
    for (int k = 2; k <= 1024; k <<= 1) {
#pragma unroll
        for (int j = k >> 1; j > 0; j >>= 1) {
            if (j >= 32) {
                // cross-lane phase: partner lane = lane ^ (j>>5), same r slot
                const int jl = j >> 5;
                const bool isLower = ((lane & jl) == 0);
                const bool descBlk = ((lane & (k >> 5)) == 0);   // (i & k) == 0
                const bool keepMax = (descBlk == isLower);
#pragma unroll
                for (int r = 0; r < 32; ++r) {
                    u64 mine  = key[r];
                    u64 other = __shfl_xor_sync(0xffffffffu, mine, jl);
                    bool q = (mine > other) == keepMax;
                    key[r] = q ? mine : other;       // 2 SEL (register pair)
                }
            } else {
                // intra-lane phase: partner register r ^ j
#pragma unroll
                for (int r = 0; r < 32; ++r) {
                    if ((r & j) == 0) {
                        const int lo = r, hi = r | j;
                        bool descBlk;
                        if (k >= 32) descBlk = ((lane & (k >> 5)) == 0); // runtime (lane bits)
                        else         descBlk = ((lo & k) == 0);          // compile-time
                        cas_fma(key[lo], key[hi], descBlk);
                    }
                }
            }
        }
    }

    // --- threshold: row (h*S + s) uses threshold[s % 16] == row % 16 ---
    float t   = thresholds[row & 15];
    float thr = 1.0f / (1.0f + expf(-t));

    // --- cumsum: lane-local total, warp exclusive scan, streamed prefix ---
    float tot = 0.0f;
#pragma unroll
    for (int r = 0; r < 32; ++r)
        tot += __uint_as_float((u32)(key[r] >> 32));

    float scan = tot;
#pragma unroll
    for (int d = 1; d < 32; d <<= 1) {
        float n = __shfl_up_sync(0xffffffffu, scan, d);
        if (lane >= d) scan += n;
    }
    float run = scan - tot;   // exclusive offset for this lane

    // --- emit padded indices (as float) + count ---
    float4* orow = reinterpret_cast<float4*>(out_idx + (size_t)row * 1024);
    int cnt = 0;
    float ov[4];
#pragma unroll
    for (int r = 0; r < 32; ++r) {
        run += __uint_as_float((u32)(key[r] >> 32));   // inclusive cumsum
        bool sel = (run <= thr);
        int id = 1023 - (int)((u32)key[r]);
        ov[r & 3] = sel ? (float)id : -1.0f;
        cnt += sel ? 1 : 0;
        if ((r & 3) == 3)
            orow[lane * 8 + (r >> 2)] = make_float4(ov[0], ov[1], ov[2], ov[3]);
    }

    if (out_counts) {
#pragma unroll
        for (int d = 16; d > 0; d >>= 1)
            cnt += __shfl_xor_sync(0xffffffffu, cnt, d);
        if (lane == 0) out_counts[row] = (float)cnt;
    }
}

extern "C" void kernel_launch(void* const* d_in, const int* in_sizes, int n_in,
                              void* d_out, int out_size)
{
    const float* atn = (const float*)d_in[0];
    const float* thr = (const float*)d_in[1];
    (void)n_in;

    const int S    = 1024;
    const int rows = in_sizes[0] / S;                 // 65536
    long long padded = (long long)rows * S;           // 67,108,864

    float* out    = (float*)d_out;
    float* counts = ((long long)out_size >= padded + rows) ? (out + padded) : nullptr;

    dim3 block(256);                                  // 8 warps = 8 rows per CTA
    dim3 grid(rows / 8);
    topp_sort_kernel<<<grid, block>>>(atn, thr, out, counts);
}

// round 13
// speedup vs baseline: 2.0005x; 1.9877x over previous
#include <cuda_runtime.h>
#include <cuda_bf16.h>
#include <cstdint>

// LearnableTopP: per row of 1024 fp32 softmax probs:
//   descending stable sort (ties -> smaller original index first),
//   inclusive cumsum, mask = cumsum <= sigmoid(threshold[s % 16]),
//   padded_idx = mask ? sorted_index : -1, counts = popcount(mask).
// Outputs as FLOAT32: [ padded_idx (rows*1024) | counts (rows) ].
//
// FAST PATH (threshold-pruned sort): with pivot PIV, if
//   s = sum{v >= PIV} > thr + EPSG   and   c = count{v >= PIV} <= 512,
// then {v >= PIV} is exactly the top-c set, the cumsum crossing lies strictly
// inside it (EPSG >> fp32 summation association error), and every excluded
// element outputs -1. So: compact kept (key,idx) into shared memory, pad to
// 512 with zero sentinels (sort to the end; add 0 to cumsum; never selected
// since run > thr there), run a 512 bitonic network (32 lanes x 16 regs),
// write tail positions 512..1023 as -1 directly.  ~2.4x fewer ALU ops than
// the full 1024 network (the kernel is ALU-pipe-bound at ~96%).
// Rows failing either condition take the exact full-1024 path (warp-uniform
// branch; ~1% of rows on this data, no correctness dependence on data).
//
// Key: ((u64)valbits << 32) | (1023 - idx); values are positive fp32 ->
// u64 compare == (value desc, idx asc), globally unique (stable ties).

using u64 = unsigned long long;
using u32 = unsigned int;

#define NW 8                       // warps (rows) per CTA
#define PIV 8.0e-4f                // pruning pivot (fallback keeps correctness)
#define EPSG 1.0e-4f               // cumsum association guard

// padded smem row: 16 slots * 8B + 8B pad = 136B -> conflict-free LDS.64
static __device__ __forceinline__ u32 slot_addr(int slot) {
    return (u32)((slot >> 4) * 136 + (slot & 15) * 8);
}

__global__ void __launch_bounds__(32 * NW) topp_kernel(
    const float* __restrict__ atn,
    const float* __restrict__ thresholds,
    float* __restrict__ out_idx,
    float* __restrict__ out_counts)
{
    __shared__ __align__(16) char smem_all[NW][4352];

    const int warp = threadIdx.x >> 5;
    const int lane = threadIdx.x & 31;
    const int row  = blockIdx.x * NW + warp;     // 65536 rows

    const float*  rowp  = atn + (size_t)row * 1024;
    const float4* rowp4 = reinterpret_cast<const float4*>(rowp);

    // --- load 32 contiguous values per lane (positions lane*32 + r) ---
    float v[32];
#pragma unroll
    for (int q = 0; q < 8; ++q) {
        float4 f = rowp4[lane * 8 + q];
        v[q*4+0] = f.x; v[q*4+1] = f.y; v[q*4+2] = f.z; v[q*4+3] = f.w;
    }

    // --- pivot statistics ---
    float sl = 0.0f; int cl = 0;
#pragma unroll
    for (int r = 0; r < 32; ++r) {
        bool f = v[r] >= PIV;
        sl += f ? v[r] : 0.0f;
        cl += f ? 1 : 0;
    }
    float s = sl; int c = cl;
#pragma unroll
    for (int d = 16; d > 0; d >>= 1) {
        s += __shfl_xor_sync(0xffffffffu, s, d);
        c += __shfl_xor_sync(0xffffffffu, c, d);
    }

    // threshold: row (h*S + sidx) uses threshold[sidx % 16] == row % 16
    float t   = thresholds[row & 15];
    float thr = 1.0f / (1.0f + expf(-t));

    float4* orow = reinterpret_cast<float4*>(out_idx + (size_t)row * 1024);

    if (s > thr + EPSG && c <= 512) {
        // ================= FAST PATH: 512-element sort =================
        char* sm = smem_all[warp];

        // zero-fill 512 slots (sentinel keys); slot lane+32q == base + 272q
        {
            u32 base = slot_addr(lane);
#pragma unroll
            for (int q = 0; q < 16; ++q)
                *reinterpret_cast<u64*>(sm + base + 272 * q) = 0ull;
        }
        __syncwarp();

        // exclusive scan of per-lane kept counts -> write offset
        int scan = cl;
#pragma unroll
        for (int d = 1; d < 32; d <<= 1) {
            int n = __shfl_up_sync(0xffffffffu, scan, d);
            if (lane >= d) scan += n;
        }
        int off = scan - cl;

        // compact kept keys into smem (any order; sort handles placement)
#pragma unroll
        for (int r = 0; r < 32; ++r) {
            if (v[r] >= PIV) {
                u64 k = ((u64)__float_as_uint(v[r]) << 32)
                      | (u32)(1023 - (lane * 32 + r));
                *reinterpret_cast<u64*>(sm + slot_addr(off)) = k;
                ++off;
            }
        }
        __syncwarp();

        // load 16 keys/lane: position i = lane*16 + r
        u64 key[16];
        {
            const char* mybase = sm + lane * 136;
#pragma unroll
            for (int r = 0; r < 16; ++r)
                key[r] = *reinterpret_cast<const u64*>(mybase + r * 8);
        }

        // bitonic sort of 512, descending over i = lane*16 + r
#pragma unroll
        for (int k = 2; k <= 512; k <<= 1) {
#pragma unroll
            for (int j = k >> 1; j > 0; j >>= 1) {
                if (j >= 16) {
                    const int jl = j >> 4;
                    const bool keepMax =
                        (((lane & (k >> 4)) == 0) == ((lane & jl) == 0));
#pragma unroll
                    for (int r = 0; r < 16; ++r) {
                        u64 mine  = key[r];
                        u64 other = __shfl_xor_sync(0xffffffffu, mine, jl);
                        bool q = (mine > other) == keepMax;
                        key[r] = q ? mine : other;
                    }
                } else {
#pragma unroll
                    for (int r = 0; r < 16; ++r) {
                        if ((r & j) == 0) {
                            const int lo = r, hi = r | j;
                            bool descBlk = (k >= 16)
                                ? ((lane & (k >> 4)) == 0)   // lane bits of i&k
                                : ((lo & k) == 0);           // compile-time
                            u64 a = key[lo], b = key[hi];
                            bool q = (a > b) == descBlk;
                            key[lo] = q ? a : b;
                            key[hi] = q ? b : a;
                        }
                    }
                }
            }
        }

        // epilogue: cumsum + emit over first 512 positions
        float tot = 0.0f;
#pragma unroll
        for (int r = 0; r < 16; ++r)
            tot += __uint_as_float((u32)(key[r] >> 32));
        float sc = tot;
#pragma unroll
        for (int d = 1; d < 32; d <<= 1) {
            float n = __shfl_up_sync(0xffffffffu, sc, d);
            if (lane >= d) sc += n;
        }
        float run = sc - tot;

        int cnt = 0; float ov[4];
#pragma unroll
        for (int r = 0; r < 16; ++r) {
            run += __uint_as_float((u32)(key[r] >> 32));
            bool sel = (run <= thr);                 // sentinels: run>thr -> false
            int id = 1023 - (int)((u32)key[r]);
            ov[r & 3] = sel ? (float)id : -1.0f;
            cnt += sel ? 1 : 0;
            if ((r & 3) == 3)
                orow[lane * 4 + (r >> 2)] = make_float4(ov[0], ov[1], ov[2], ov[3]);
        }

        // tail positions 512..1023 are provably past the crossing -> -1
        float4 m1 = make_float4(-1.0f, -1.0f, -1.0f, -1.0f);
#pragma unroll
        for (int q = 0; q < 4; ++q)
            orow[128 + lane * 4 + q] = m1;

        if (out_counts) {
#pragma unroll
            for (int d = 16; d > 0; d >>= 1)
                cnt += __shfl_xor_sync(0xffffffffu, cnt, d);
            if (lane == 0) out_counts[row] = (float)cnt;
        }
    } else {
        // ================= FULL PATH: exact 1024 sort (R5) =================
        u64 key[32];
#pragma unroll
        for (int r = 0; r < 32; ++r)
            key[r] = ((u64)__float_as_uint(v[r]) << 32)
                   | (u32)(1023 - (lane * 32 + r));

#pragma unroll
        for (int k = 2; k <= 1024; k <<= 1) {
#pragma unroll
            for (int j = k >> 1; j > 0; j >>= 1) {
                if (j >= 32) {
                    const int jl = j >> 5;
                    const bool keepMax =
                        (((lane & (k >> 5)) == 0) == ((lane & jl) == 0));
#pragma unroll
                    for (int r = 0; r < 32; ++r) {
                        u64 mine  = key[r];
                        u64 other = __shfl_xor_sync(0xffffffffu, mine, jl);
                        bool q = (mine > other) == keepMax;
                        key[r] = q ? mine : other;
                    }
                } else {
#pragma unroll
                    for (int r = 0; r < 32; ++r) {
                        if ((r & j) == 0) {
                            const int lo = r, hi = r | j;
                            bool descBlk = (k >= 32)
                                ? ((lane & (k >> 5)) == 0)
                                : ((lo & k) == 0);
                            u64 a = key[lo], b = key[hi];
                            bool q = (a > b) == descBlk;
                            key[lo] = q ? a : b;
                            key[hi] = q ? b : a;
                        }
                    }
                }
            }
        }

        float tot = 0.0f;
#pragma unroll
        for (int r = 0; r < 32; ++r)
            tot += __uint_as_float((u32)(key[r] >> 32));
        float sc = tot;
#pragma unroll
        for (int d = 1; d < 32; d <<= 1) {
            float n = __shfl_up_sync(0xffffffffu, sc, d);
            if (lane >= d) sc += n;
        }
        float run = sc - tot;

        int cnt = 0; float ov[4];
#pragma unroll
        for (int r = 0; r < 32; ++r) {
            run += __uint_as_float((u32)(key[r] >> 32));
            bool sel = (run <= thr);
            int id = 1023 - (int)((u32)key[r]);
            ov[r & 3] = sel ? (float)id : -1.0f;
            cnt += sel ? 1 : 0;
            if ((r & 3) == 3)
                orow[lane * 8 + (r >> 2)] = make_float4(ov[0], ov[1], ov[2], ov[3]);
        }

        if (out_counts) {
#pragma unroll
            for (int d = 16; d > 0; d >>= 1)
                cnt += __shfl_xor_sync(0xffffffffu, cnt, d);
            if (lane == 0) out_counts[row] = (float)cnt;
        }
    }
}

extern "C" void kernel_launch(void* const* d_in, const int* in_sizes, int n_in,
                              void* d_out, int out_size)
{
    const float* atn = (const float*)d_in[0];
    const float* thr = (const float*)d_in[1];
    (void)n_in;

    const int S    = 1024;
    const int rows = in_sizes[0] / S;                 // 65536
    long long padded = (long long)rows * S;           // 67,108,864

    float* out    = (float*)d_out;
    float* counts = ((long long)out_size >= padded + rows) ? (out + padded) : nullptr;

    dim3 block(32 * NW);                              // 8 warps = 8 rows per CTA
    dim3 grid(rows / NW);
    topp_kernel<<<grid, block>>>(atn, thr, out, counts);
}

// round 14
// speedup vs baseline: 2.0842x; 1.0419x over previous
#include <cuda_runtime.h>
#include <cuda_bf16.h>
#include <cstdint>

// LearnableTopP: per row of 1024 fp32 softmax probs:
//   descending stable sort (ties -> smaller original index first),
//   inclusive cumsum, mask = cumsum <= sigmoid(threshold[s % 16]),
//   padded_idx = mask ? sorted_index : -1, counts = popcount(mask).
// Outputs as FLOAT32: [ padded_idx (rows*1024) | counts (rows) ].
//
// FAST PATH (threshold-pruned sort): with pivot PIV, if
//   s = sum{v >= PIV} > thr + EPSG   and   c = count{v >= PIV} <= 512,
// then {v >= PIV} is exactly the top-c set, the cumsum crossing lies strictly
// inside it, and every excluded element outputs -1: sort only 512.
// R14: two-pass row read (no v[32] kept live) + __launch_bounds__(256,4)
// to cap regs at 64 -> occupancy 2 -> 4 CTAs/SM (was the limiter: regs=100,
// occ 23.8%, alu pipe starved at 72.9% vs 96% when saturated).
// Full-1024 exact fallback (warp-uniform, ~1% rows) may spill; acceptable.
//
// Key: ((u64)valbits << 32) | (1023 - idx); values are positive fp32 ->
// u64 compare == (value desc, idx asc), globally unique (stable ties).

using u64 = unsigned long long;
using u32 = unsigned int;

#define NW 8                       // warps (rows) per CTA
#define PIV 8.0e-4f                // pruning pivot (fallback keeps correctness)
#define EPSG 1.0e-4f               // cumsum association guard

// padded smem row: 16 slots * 8B + 8B pad = 136B -> conflict-free LDS.64
static __device__ __forceinline__ u32 slot_addr(int slot) {
    return (u32)((slot >> 4) * 136 + (slot & 15) * 8);
}

__global__ void __launch_bounds__(32 * NW, 4) topp_kernel(
    const float* __restrict__ atn,
    const float* __restrict__ thresholds,
    float* __restrict__ out_idx,
    float* __restrict__ out_counts)
{
    __shared__ __align__(16) char smem_all[NW][4352];

    const int warp = threadIdx.x >> 5;
    const int lane = threadIdx.x & 31;
    const int row  = blockIdx.x * NW + warp;     // 65536 rows

    const float*  rowp  = atn + (size_t)row * 1024;
    const float4* rowp4 = reinterpret_cast<const float4*>(rowp);

    // --- pass 1: pivot statistics (streaming, no value array kept) ---
    float sl = 0.0f; int cl = 0;
#pragma unroll
    for (int q = 0; q < 8; ++q) {
        float4 f = rowp4[lane * 8 + q];
        bool f0 = f.x >= PIV, f1 = f.y >= PIV, f2 = f.z >= PIV, f3 = f.w >= PIV;
        sl += f0 ? f.x : 0.0f;  cl += f0 ? 1 : 0;
        sl += f1 ? f.y : 0.0f;  cl += f1 ? 1 : 0;
        sl += f2 ? f.z : 0.0f;  cl += f2 ? 1 : 0;
        sl += f3 ? f.w : 0.0f;  cl += f3 ? 1 : 0;
    }
    float s = sl; int c = cl;
#pragma unroll
    for (int d = 16; d > 0; d >>= 1) {
        s += __shfl_xor_sync(0xffffffffu, s, d);
        c += __shfl_xor_sync(0xffffffffu, c, d);
    }

    // threshold: row (h*S + sidx) uses threshold[sidx % 16] == row % 16
    float t   = thresholds[row & 15];
    float thr = 1.0f / (1.0f + expf(-t));

    float4* orow = reinterpret_cast<float4*>(out_idx + (size_t)row * 1024);

    if (s > thr + EPSG && c <= 512) {
        // ================= FAST PATH: 512-element sort =================
        char* sm = smem_all[warp];

        // zero-fill 512 slots (sentinel keys); slot lane+32q == base + 272q
        {
            u32 base = slot_addr(lane);
#pragma unroll
            for (int q = 0; q < 16; ++q)
                *reinterpret_cast<u64*>(sm + base + 272 * q) = 0ull;
        }
        __syncwarp();

        // exclusive scan of per-lane kept counts -> write offset
        int scan = cl;
#pragma unroll
        for (int d = 1; d < 32; d <<= 1) {
            int n = __shfl_up_sync(0xffffffffu, scan, d);
            if (lane >= d) scan += n;
        }
        int off = scan - cl;

        // pass 2: re-read row (L1-resident) and compact kept keys into smem
#pragma unroll
        for (int q = 0; q < 8; ++q) {
            float4 f = rowp4[lane * 8 + q];
            int base = (lane << 5) + (q << 2);
            float vv[4] = {f.x, f.y, f.z, f.w};
#pragma unroll
            for (int u = 0; u < 4; ++u) {
                if (vv[u] >= PIV) {
                    u64 k = ((u64)__float_as_uint(vv[u]) << 32)
                          | (u32)(1023 - (base + u));
                    *reinterpret_cast<u64*>(sm + slot_addr(off)) = k;
                    ++off;
                }
            }
        }
        __syncwarp();

        // load 16 keys/lane: position i = lane*16 + r
        u64 key[16];
        {
            const char* mybase = sm + lane * 136;
#pragma unroll
            for (int r = 0; r < 16; ++r)
                key[r] = *reinterpret_cast<const u64*>(mybase + r * 8);
        }

        // bitonic sort of 512, descending over i = lane*16 + r
#pragma unroll
        for (int k = 2; k <= 512; k <<= 1) {
#pragma unroll
            for (int j = k >> 1; j > 0; j >>= 1) {
                if (j >= 16) {
                    const int jl = j >> 4;
                    const bool keepMax =
                        (((lane & (k >> 4)) == 0) == ((lane & jl) == 0));
#pragma unroll
                    for (int r = 0; r < 16; ++r) {
                        u64 mine  = key[r];
                        u64 other = __shfl_xor_sync(0xffffffffu, mine, jl);
                        bool q = (mine > other) == keepMax;
                        key[r] = q ? mine : other;
                    }
                } else {
#pragma unroll
                    for (int r = 0; r < 16; ++r) {
                        if ((r & j) == 0) {
                            const int lo = r, hi = r | j;
                            bool descBlk = (k >= 16)
                                ? ((lane & (k >> 4)) == 0)   // lane bits of i&k
                                : ((lo & k) == 0);           // compile-time
                            u64 a = key[lo], b = key[hi];
                            bool q = (a > b) == descBlk;
                            key[lo] = q ? a : b;
                            key[hi] = q ? b : a;
                        }
                    }
                }
            }
        }

        // epilogue: cumsum + emit over first 512 positions
        float tot = 0.0f;
#pragma unroll
        for (int r = 0; r < 16; ++r)
            tot += __uint_as_float((u32)(key[r] >> 32));
        float sc = tot;
#pragma unroll
        for (int d = 1; d < 32; d <<= 1) {
            float n = __shfl_up_sync(0xffffffffu, sc, d);
            if (lane >= d) sc += n;
        }
        float run = sc - tot;

        int cnt = 0; float ov[4];
#pragma unroll
        for (int r = 0; r < 16; ++r) {
            run += __uint_as_float((u32)(key[r] >> 32));
            bool sel = (run <= thr);                 // sentinels: run>thr -> false
            int id = 1023 - (int)((u32)key[r]);
            ov[r & 3] = sel ? (float)id : -1.0f;
            cnt += sel ? 1 : 0;
            if ((r & 3) == 3)
                orow[lane * 4 + (r >> 2)] = make_float4(ov[0], ov[1], ov[2], ov[3]);
        }

        // tail positions 512..1023 are provably past the crossing -> -1
        float4 m1 = make_float4(-1.0f, -1.0f, -1.0f, -1.0f);
#pragma unroll
        for (int q = 0; q < 4; ++q)
            orow[128 + lane * 4 + q] = m1;

        if (out_counts) {
#pragma unroll
            for (int d = 16; d > 0; d >>= 1)
                cnt += __shfl_xor_sync(0xffffffffu, cnt, d);
            if (lane == 0) out_counts[row] = (float)cnt;
        }
    } else {
        // ============ FULL PATH: exact 1024 sort (rare; may spill) ============
        u64 key[32];
#pragma unroll
        for (int q = 0; q < 8; ++q) {
            float4 f = rowp4[lane * 8 + q];
            int base = (lane << 5) + (q << 2);
            key[q*4+0] = ((u64)__float_as_uint(f.x) << 32) | (u32)(1023 - (base + 0));
            key[q*4+1] = ((u64)__float_as_uint(f.y) << 32) | (u32)(1023 - (base + 1));
            key[q*4+2] = ((u64)__float_as_uint(f.z) << 32) | (u32)(1023 - (base + 2));
            key[q*4+3] = ((u64)__float_as_uint(f.w) << 32) | (u32)(1023 - (base + 3));
        }

#pragma unroll
        for (int k = 2; k <= 1024; k <<= 1) {
#pragma unroll
            for (int j = k >> 1; j > 0; j >>= 1) {
                if (j >= 32) {
                    const int jl = j >> 5;
                    const bool keepMax =
                        (((lane & (k >> 5)) == 0) == ((lane & jl) == 0));
#pragma unroll
                    for (int r = 0; r < 32; ++r) {
                        u64 mine  = key[r];
                        u64 other = __shfl_xor_sync(0xffffffffu, mine, jl);
                        bool q = (mine > other) == keepMax;
                        key[r] = q ? mine : other;
                    }
                } else {
#pragma unroll
                    for (int r = 0; r < 32; ++r) {
                        if ((r & j) == 0) {
                            const int lo = r, hi = r | j;
                            bool descBlk = (k >= 32)
                                ? ((lane & (k >> 5)) == 0)
                                : ((lo & k) == 0);
                            u64 a = key[lo], b = key[hi];
                            bool q = (a > b) == descBlk;
                            key[lo] = q ? a : b;
                            key[hi] = q ? b : a;
                        }
                    }
                }
            }
        }

        float tot = 0.0f;
#pragma unroll
        for (int r = 0; r < 32; ++r)
            tot += __uint_as_float((u32)(key[r] >> 32));
        float sc = tot;
#pragma unroll
        for (int d = 1; d < 32; d <<= 1) {
            float n = __shfl_up_sync(0xffffffffu, sc, d);
            if (lane >= d) sc += n;
        }
        float run = sc - tot;

        int cnt = 0; float ov[4];
#pragma unroll
        for (int r = 0; r < 32; ++r) {
            run += __uint_as_float((u32)(key[r] >> 32));
            bool sel = (run <= thr);
            int id = 1023 - (int)((u32)key[r]);
            ov[r & 3] = sel ? (float)id : -1.0f;
            cnt += sel ? 1 : 0;
            if ((r & 3) == 3)
                orow[lane * 8 + (r >> 2)] = make_float4(ov[0], ov[1], ov[2], ov[3]);
        }

        if (out_counts) {
#pragma unroll
            for (int d = 16; d > 0; d >>= 1)
                cnt += __shfl_xor_sync(0xffffffffu, cnt, d);
            if (lane == 0) out_counts[row] = (float)cnt;
        }
    }
}

extern "C" void kernel_launch(void* const* d_in, const int* in_sizes, int n_in,
                              void* d_out, int out_size)
{
    const float* atn = (const float*)d_in[0];
    const float* thr = (const float*)d_in[1];
    (void)n_in;

    const int S    = 1024;
    const int rows = in_sizes[0] / S;                 // 65536
    long long padded = (long long)rows * S;           // 67,108,864

    float* out    = (float*)d_out;
    float* counts = ((long long)out_size >= padded + rows) ? (out + padded) : nullptr;

    dim3 block(32 * NW);                              // 8 warps = 8 rows per CTA
    dim3 grid(rows / NW);
    topp_kernel<<<grid, block>>>(atn, thr, out, counts);
}

// round 15
// speedup vs baseline: 2.1719x; 1.0421x over previous
#include <cuda_runtime.h>
#include <cuda_bf16.h>
#include <cstdint>

// LearnableTopP: per row of 1024 fp32 softmax probs:
//   descending stable sort (ties -> smaller original index first),
//   inclusive cumsum, mask = cumsum <= sigmoid(threshold[s % 16]),
//   padded_idx = mask ? sorted_index : -1, counts = popcount(mask).
// Outputs as FLOAT32: [ padded_idx (rows*1024) | counts (rows) ].
//
// FAST PATH (threshold-pruned): if s = sum{v>=PIV} > thr + EPSG and
// c = count{v>=PIV} <= 512, the kept set is exactly the top-c, the crossing
// lies inside it, everything else is -1 -> sort only 512 (zero-sentinel pad).
// R15: (1) __launch_bounds__(256,5) -> 51-reg cap, 40 warps/SM;
//      (2) local 16-elem stage = Batcher odd-even mergesort (63 comparators
//          vs 80 for bitonic k=2..16), direction (lane&1)==0 — exactly the
//          block pattern bitonic level k=32 expects; result bit-identical;
//      (3) sentinel fill only [c,512) (disjoint from compaction writes).
// Exact full-1024 fallback for rows failing the guard (warp-uniform, ~1%).
//
// Key: ((u64)valbits << 32) | (1023 - idx); positive fp32 -> u64 compare ==
// (value desc, idx asc), globally unique (stable ties).

using u64 = unsigned long long;
using u32 = unsigned int;

#define NW 8                       // warps (rows) per CTA
#define PIV 8.0e-4f                // pruning pivot (fallback keeps correctness)
#define EPSG 1.0e-4f               // cumsum association guard

static __device__ __forceinline__ void cas(u64 &A, u64 &B, bool dir) {
    u64 a = A, b = B;
    bool q = (a > b) == dir;       // dir=true: A keeps the larger key
    A = q ? a : b;
    B = q ? b : a;
}

// ---- Batcher odd-even mergesort, compile-time generated (canonical) ----
template<int LO, int N, int R>
static __device__ __forceinline__ void oe_merge(u64* k, bool dir) {
    constexpr int M = 2 * R;
    if constexpr (M < N) {
        oe_merge<LO, N, M>(k, dir);
        oe_merge<LO + R, N, M>(k, dir);
#pragma unroll
        for (int i = LO + R; i + R < LO + N; i += M)
            cas(k[i], k[i + R], dir);
    } else {
        cas(k[LO], k[LO + R], dir);
    }
}
template<int LO, int N>
static __device__ __forceinline__ void oe_sort(u64* k, bool dir) {
    if constexpr (N > 1) {
        oe_sort<LO, N / 2>(k, dir);
        oe_sort<LO + N / 2, N / 2>(k, dir);
        oe_merge<LO, N, 1>(k, dir);
    }
}

// padded smem row: 16 slots * 8B + 8B pad = 136B -> conflict-free LDS.64
static __device__ __forceinline__ u32 slot_addr(int slot) {
    return (u32)((slot >> 4) * 136 + (slot & 15) * 8);
}

__global__ void __launch_bounds__(32 * NW, 5) topp_kernel(
    const float* __restrict__ atn,
    const float* __restrict__ thresholds,
    float* __restrict__ out_idx,
    float* __restrict__ out_counts)
{
    __shared__ __align__(16) char smem_all[NW][4352];

    const int warp = threadIdx.x >> 5;
    const int lane = threadIdx.x & 31;
    const int row  = blockIdx.x * NW + warp;     // 65536 rows

    const float*  rowp  = atn + (size_t)row * 1024;
    const float4* rowp4 = reinterpret_cast<const float4*>(rowp);

    // --- pass 1: pivot statistics (streaming, no value array kept) ---
    float sl = 0.0f; int cl = 0;
#pragma unroll
    for (int q = 0; q < 8; ++q) {
        float4 f = rowp4[lane * 8 + q];
        bool f0 = f.x >= PIV, f1 = f.y >= PIV, f2 = f.z >= PIV, f3 = f.w >= PIV;
        sl += f0 ? f.x : 0.0f;  cl += f0 ? 1 : 0;
        sl += f1 ? f.y : 0.0f;  cl += f1 ? 1 : 0;
        sl += f2 ? f.z : 0.0f;  cl += f2 ? 1 : 0;
        sl += f3 ? f.w : 0.0f;  cl += f3 ? 1 : 0;
    }
    float s = sl; int c = cl;
#pragma unroll
    for (int d = 16; d > 0; d >>= 1) {
        s += __shfl_xor_sync(0xffffffffu, s, d);
        c += __shfl_xor_sync(0xffffffffu, c, d);
    }

    // threshold: row (h*S + sidx) uses threshold[sidx % 16] == row % 16
    float t   = thresholds[row & 15];
    float thr = 1.0f / (1.0f + expf(-t));

    float4* orow = reinterpret_cast<float4*>(out_idx + (size_t)row * 1024);

    if (s > thr + EPSG && c <= 512) {
        // ================= FAST PATH: 512-element sort =================
        char* sm = smem_all[warp];

        // sentinel-fill only slots [c, 512) (compaction writes [0, c))
        for (int sl2 = c + lane; sl2 < 512; sl2 += 32)
            *reinterpret_cast<u64*>(sm + slot_addr(sl2)) = 0ull;

        // exclusive scan of per-lane kept counts -> write offset
        int scan = cl;
#pragma unroll
        for (int d = 1; d < 32; d <<= 1) {
            int n = __shfl_up_sync(0xffffffffu, scan, d);
            if (lane >= d) scan += n;
        }
        int off = scan - cl;

        // pass 2: re-read row (L1-resident) and compact kept keys into smem
#pragma unroll
        for (int q = 0; q < 8; ++q) {
            float4 f = rowp4[lane * 8 + q];
            int base = (lane << 5) + (q << 2);
            float vv[4] = {f.x, f.y, f.z, f.w};
#pragma unroll
            for (int u = 0; u < 4; ++u) {
                if (vv[u] >= PIV) {
                    u64 k = ((u64)__float_as_uint(vv[u]) << 32)
                          | (u32)(1023 - (base + u));
                    *reinterpret_cast<u64*>(sm + slot_addr(off)) = k;
                    ++off;
                }
            }
        }
        __syncwarp();

        // load 16 keys/lane: position i = lane*16 + r
        u64 key[16];
        {
            const char* mybase = sm + lane * 136;
#pragma unroll
            for (int r = 0; r < 16; ++r)
                key[r] = *reinterpret_cast<const u64*>(mybase + r * 8);
        }

        // local stage: sort own 16 keys; block (=lane) sorted descending iff
        // (i & 16)==0 at level k=16 boundary <=> even lane. (Replaces bitonic
        // levels k=2..16; identical result, 63 vs 80 comparators.)
        oe_sort<0, 16>(key, (lane & 1) == 0);

        // bitonic merge levels k=32..512, descending over i = lane*16 + r
#pragma unroll
        for (int k = 32; k <= 512; k <<= 1) {
#pragma unroll
            for (int j = k >> 1; j > 0; j >>= 1) {
                if (j >= 16) {
                    const int jl = j >> 4;
                    const bool keepMax =
                        (((lane & (k >> 4)) == 0) == ((lane & jl) == 0));
#pragma unroll
                    for (int r = 0; r < 16; ++r) {
                        u64 mine  = key[r];
                        u64 other = __shfl_xor_sync(0xffffffffu, mine, jl);
                        bool q = (mine > other) == keepMax;
                        key[r] = q ? mine : other;
                    }
                } else {
                    const bool descBlk = ((lane & (k >> 4)) == 0);
#pragma unroll
                    for (int r = 0; r < 16; ++r) {
                        if ((r & j) == 0)
                            cas(key[r], key[r | j], descBlk);
                    }
                }
            }
        }

        // epilogue: cumsum + emit over first 512 positions
        float tot = 0.0f;
#pragma unroll
        for (int r = 0; r < 16; ++r)
            tot += __uint_as_float((u32)(key[r] >> 32));
        float sc = tot;
#pragma unroll
        for (int d = 1; d < 32; d <<= 1) {
            float n = __shfl_up_sync(0xffffffffu, sc, d);
            if (lane >= d) sc += n;
        }
        float run = sc - tot;

        int cnt = 0; float ov[4];
#pragma unroll
        for (int r = 0; r < 16; ++r) {
            run += __uint_as_float((u32)(key[r] >> 32));
            bool sel = (run <= thr);                 // sentinels: run>thr -> false
            int id = 1023 - (int)((u32)key[r]);
            ov[r & 3] = sel ? (float)id : -1.0f;
            cnt += sel ? 1 : 0;
            if ((r & 3) == 3)
                orow[lane * 4 + (r >> 2)] = make_float4(ov[0], ov[1], ov[2], ov[3]);
        }

        // tail positions 512..1023 are provably past the crossing -> -1
        float4 m1 = make_float4(-1.0f, -1.0f, -1.0f, -1.0f);
#pragma unroll
        for (int q = 0; q < 4; ++q)
            orow[128 + lane * 4 + q] = m1;

        if (out_counts) {
#pragma unroll
            for (int d = 16; d > 0; d >>= 1)
                cnt += __shfl_xor_sync(0xffffffffu, cnt, d);
            if (lane == 0) out_counts[row] = (float)cnt;
        }
    } else {
        // ============ FULL PATH: exact 1024 sort (rare; may spill) ============
        u64 key[32];
#pragma unroll
        for (int q = 0; q < 8; ++q) {
            float4 f = rowp4[lane * 8 + q];
            int base = (lane << 5) + (q << 2);
            key[q*4+0] = ((u64)__float_as_uint(f.x) << 32) | (u32)(1023 - (base + 0));
            key[q*4+1] = ((u64)__float_as_uint(f.y) << 32) | (u32)(1023 - (base + 1));
            key[q*4+2] = ((u64)__float_as_uint(f.z) << 32) | (u32)(1023 - (base + 2));
            key[q*4+3] = ((u64)__float_as_uint(f.w) << 32) | (u32)(1023 - (base + 3));
        }

#pragma unroll
        for (int k = 2; k <= 1024; k <<= 1) {
#pragma unroll
            for (int j = k >> 1; j > 0; j >>= 1) {
                if (j >= 32) {
                    const int jl = j >> 5;
                    const bool keepMax =
                        (((lane & (k >> 5)) == 0) == ((lane & jl) == 0));
#pragma unroll
                    for (int r = 0; r < 32; ++r) {
                        u64 mine  = key[r];
                        u64 other = __shfl_xor_sync(0xffffffffu, mine, jl);
                        bool q = (mine > other) == keepMax;
                        key[r] = q ? mine : other;
                    }
                } else {
#pragma unroll
                    for (int r = 0; r < 32; ++r) {
                        if ((r & j) == 0) {
                            bool descBlk = (k >= 32)
                                ? ((lane & (k >> 5)) == 0)
                                : ((r & k) == 0);
                            cas(key[r], key[r | j], descBlk);
                        }
                    }
                }
            }
        }

        float tot = 0.0f;
#pragma unroll
        for (int r = 0; r < 32; ++r)
            tot += __uint_as_float((u32)(key[r] >> 32));
        float sc = tot;
#pragma unroll
        for (int d = 1; d < 32; d <<= 1) {
            float n = __shfl_up_sync(0xffffffffu, sc, d);
            if (lane >= d) sc += n;
        }
        float run = sc - tot;

        int cnt = 0; float ov[4];
#pragma unroll
        for (int r = 0; r < 32; ++r) {
            run += __uint_as_float((u32)(key[r] >> 32));
            bool sel = (run <= thr);
            int id = 1023 - (int)((u32)key[r]);
            ov[r & 3] = sel ? (float)id : -1.0f;
            cnt += sel ? 1 : 0;
            if ((r & 3) == 3)
                orow[lane * 8 + (r >> 2)] = make_float4(ov[0], ov[1], ov[2], ov[3]);
        }

        if (out_counts) {
#pragma unroll
            for (int d = 16; d > 0; d >>= 1)
                cnt += __shfl_xor_sync(0xffffffffu, cnt, d);
            if (lane == 0) out_counts[row] = (float)cnt;
        }
    }
}

extern "C" void kernel_launch(void* const* d_in, const int* in_sizes, int n_in,
                              void* d_out, int out_size)
{
    const float* atn = (const float*)d_in[0];
    const float* thr = (const float*)d_in[1];
    (void)n_in;

    const int S    = 1024;
    const int rows = in_sizes[0] / S;                 // 65536
    long long padded = (long long)rows * S;           // 67,108,864

    float* out    = (float*)d_out;
    float* counts = ((long long)out_size >= padded + rows) ? (out + padded) : nullptr;

    dim3 block(32 * NW);                              // 8 warps = 8 rows per CTA
    dim3 grid(rows / NW);
    topp_kernel<<<grid, block>>>(atn, thr, out, counts);
}

// round 17
// speedup vs baseline: 2.2479x; 1.0350x over previous
#include <cuda_runtime.h>
#include <cuda_bf16.h>
#include <cstdint>

// LearnableTopP: per row of 1024 fp32 softmax probs:
//   descending stable sort (ties -> smaller original index first),
//   inclusive cumsum, mask = cumsum <= sigmoid(threshold[s % 16]),
//   padded_idx = mask ? sorted_index : -1, counts = popcount(mask).
// Outputs as FLOAT32: [ padded_idx (rows*1024) | counts (rows) ].
//
// R16 FAST PATH (two-pivot, two concurrent half-warp sorts): if
//   s    = sum{v >= PIVLO} > thr + EPSG,
//   ch   = count{v >= PIVHI} <= 256,
//   cm   = count{PIVLO <= v < PIVHI} <= 256,
// then HIGH = {v>=PIVHI} and MID = {PIVLO<=v<PIVHI} partition the kept set
// with every HIGH key > every MID key (ties at PIVHI all go HIGH), so
// concat(sort HIGH, sort MID) is the global sorted kept prefix, the cumsum
// crossing lies inside it, and all other positions are -1.
// Lanes 0-15 sort HIGH (256 net, 16 regs/lane), lanes 16-31 sort MID —
// concurrently; shfl.xor distances <= 8 never cross the half-warp.
// Lane-major layout == concatenated order, so one warp cumsum covers both.
// Zero sentinels pad [ch,256) and [256+cm,512): contribute 0 to cumsum and
// are excluded from emission/count by the real-element predicate.
// Rows failing any guard take the exact full-1024 path (warp-uniform).
//
// Key: ((u64)valbits << 32) | (1023 - idx); positive fp32 -> u64 compare ==
// (value desc, idx asc), globally unique (stable ties).

using u64 = unsigned long long;
using u32 = unsigned int;

#define NW 8                       // warps (rows) per CTA
#define PIVLO 8.0e-4f              // kept-set pivot
#define PIVHI 1.42e-3f             // HIGH/MID split pivot (~median of kept)
#define EPSG 1.0e-4f               // cumsum association guard

static __device__ __forceinline__ void cas(u64 &A, u64 &B, bool dir) {
    u64 a = A, b = B;
    bool q = (a > b) == dir;       // dir=true: A keeps the larger key
    A = q ? a : b;
    B = q ? b : a;
}

// ---- Batcher odd-even mergesort, compile-time generated (canonical) ----
template<int LO, int N, int R>
static __device__ __forceinline__ void oe_merge(u64* k, bool dir) {
    constexpr int M = 2 * R;
    if constexpr (M < N) {
        oe_merge<LO, N, M>(k, dir);
        oe_merge<LO + R, N, M>(k, dir);
#pragma unroll
        for (int i = LO + R; i + R < LO + N; i += M)
            cas(k[i], k[i + R], dir);
    } else {
        cas(k[LO], k[LO + R], dir);
    }
}
template<int LO, int N>
static __device__ __forceinline__ void oe_sort(u64* k, bool dir) {
    if constexpr (N > 1) {
        oe_sort<LO, N / 2>(k, dir);
        oe_sort<LO + N / 2, N / 2>(k, dir);
        oe_merge<LO, N, 1>(k, dir);
    }
}

// padded smem slot: 136B per 16-slot row, +8B skew for the upper block so
// lanes l and l+16 (same r) hit different banks.
static __device__ __forceinline__ u32 slot_addr(int slot) {
    return (u32)((slot >> 4) * 136 + (slot & 15) * 8 + ((slot >> 8) << 3));
}

__global__ void __launch_bounds__(32 * NW, 5) topp_kernel(
    const float* __restrict__ atn,
    const float* __restrict__ thresholds,
    float* __restrict__ out_idx,
    float* __restrict__ out_counts)
{
    __shared__ __align__(16) char smem_all[NW][4352];

    const int warp = threadIdx.x >> 5;
    const int lane = threadIdx.x & 31;
    const int row  = blockIdx.x * NW + warp;     // 65536 rows

    const float*  rowp  = atn + (size_t)row * 1024;
    const float4* rowp4 = reinterpret_cast<const float4*>(rowp);

    // --- pass 1: pivot statistics (streaming) ---
    float sl = 0.0f; int cl = 0, chl = 0;
#pragma unroll
    for (int q = 0; q < 8; ++q) {
        float4 f = rowp4[lane * 8 + q];
        float vv[4] = {f.x, f.y, f.z, f.w};
#pragma unroll
        for (int u = 0; u < 4; ++u) {
            bool fl = vv[u] >= PIVLO, fh = vv[u] >= PIVHI;
            sl  += fl ? vv[u] : 0.0f;
            cl  += fl ? 1 : 0;
            chl += fh ? 1 : 0;
        }
    }
    float s = sl; int c = cl, ch = chl;
#pragma unroll
    for (int d = 16; d > 0; d >>= 1) {
        s  += __shfl_xor_sync(0xffffffffu, s, d);
        c  += __shfl_xor_sync(0xffffffffu, c, d);
        ch += __shfl_xor_sync(0xffffffffu, ch, d);
    }
    const int cm = c - ch;

    // threshold: row (h*S + sidx) uses threshold[sidx % 16] == row % 16
    float t   = thresholds[row & 15];
    float thr = 1.0f / (1.0f + expf(-t));

    float* orow_s = out_idx + (size_t)row * 1024;

    if (s > thr + EPSG && ch <= 256 && cm <= 256) {
        // ========== FAST PATH: two concurrent half-warp 256 sorts ==========
        char* sm = smem_all[warp];

        // sentinel-fill gaps [ch,256) and [256+cm,512)
        for (int z = ch + lane; z < 256; z += 32)
            *reinterpret_cast<u64*>(sm + slot_addr(z)) = 0ull;
        for (int z = 256 + cm + lane; z < 512; z += 32)
            *reinterpret_cast<u64*>(sm + slot_addr(z)) = 0ull;

        // exclusive scans of per-lane HIGH and MID counts
        int cml = cl - chl;
        int scanH = chl, scanM = cml;
#pragma unroll
        for (int d = 1; d < 32; d <<= 1) {
            int nH = __shfl_up_sync(0xffffffffu, scanH, d);
            int nM = __shfl_up_sync(0xffffffffu, scanM, d);
            if (lane >= d) { scanH += nH; scanM += nM; }
        }
        int offH = scanH - chl;
        int offM = 256 + scanM - cml;

        // pass 2: re-read row (L1-resident), compact into HIGH/MID regions
#pragma unroll
        for (int q = 0; q < 8; ++q) {
            float4 f = rowp4[lane * 8 + q];
            int base = (lane << 5) + (q << 2);
            float vv[4] = {f.x, f.y, f.z, f.w};
#pragma unroll
            for (int u = 0; u < 4; ++u) {
                if (vv[u] >= PIVLO) {
                    bool fh = vv[u] >= PIVHI;
                    int slot = fh ? offH : offM;
                    u64 k = ((u64)__float_as_uint(vv[u]) << 32)
                          | (u32)(1023 - (base + u));
                    *reinterpret_cast<u64*>(sm + slot_addr(slot)) = k;
                    if (fh) ++offH; else ++offM;
                }
            }
        }
        __syncwarp();

        const int hl = lane & 15;       // lane within half
        const int hs = lane >> 4;       // 0 = HIGH block, 1 = MID block

        // load 16 keys: block position p = hl*16 + r  (slot hs*256 + p)
        u64 key[16];
        {
            const char* mybase = sm + (u32)((hs * 16 + hl) * 136 + hs * 8);
#pragma unroll
            for (int r = 0; r < 16; ++r)
                key[r] = *reinterpret_cast<const u64*>(mybase + r * 8);
        }

        // local 16-sort; block (=hl) descending iff even hl
        oe_sort<0, 16>(key, (hl & 1) == 0);

        // bitonic merge levels k=32..256 within each half-warp
#pragma unroll
        for (int k = 32; k <= 256; k <<= 1) {
#pragma unroll
            for (int j = k >> 1; j > 0; j >>= 1) {
                if (j >= 16) {
                    const int jl = j >> 4;              // <= 8: stays in half
                    const bool keepMax =
                        (((hl & (k >> 4)) == 0) == ((hl & jl) == 0));
#pragma unroll
                    for (int r = 0; r < 16; ++r) {
                        u64 mine  = key[r];
                        u64 other = __shfl_xor_sync(0xffffffffu, mine, jl);
                        bool q = (mine > other) == keepMax;
                        key[r] = q ? mine : other;
                    }
                } else {
                    const bool descBlk = ((hl & (k >> 4)) == 0);
#pragma unroll
                    for (int r = 0; r < 16; ++r) {
                        if ((r & j) == 0)
                            cas(key[r], key[r | j], descBlk);
                    }
                }
            }
        }

        // cumsum over concatenated order (lane-major == HIGH then MID;
        // sentinels contribute 0)
        float tot = 0.0f;
#pragma unroll
        for (int r = 0; r < 16; ++r)
            tot += __uint_as_float((u32)(key[r] >> 32));
        float sc = tot;
#pragma unroll
        for (int d = 1; d < 32; d <<= 1) {
            float n = __shfl_up_sync(0xffffffffu, sc, d);
            if (lane >= d) sc += n;
        }
        float run = sc - tot;

        // emit: real positions map to global sorted rank jbase + p
        const int climit = hs ? cm : ch;
        const int jbase  = hs ? ch : 0;
        int cnt = 0;
#pragma unroll
        for (int r = 0; r < 16; ++r) {
            run += __uint_as_float((u32)(key[r] >> 32));
            int p = hl * 16 + r;
            bool real = p < climit;
            bool sel  = (run <= thr) && real;
            if (real) {
                int id = 1023 - (int)((u32)key[r]);
                orow_s[jbase + p] = sel ? (float)id : -1.0f;
            }
            cnt += sel ? 1 : 0;
        }

        // tail ranks [c, 1024) -> -1 (provably past the crossing)
        {
            int a0 = (c + 3) & ~3;
            if (lane < a0 - c) orow_s[c + lane] = -1.0f;
            float4 m1 = make_float4(-1.0f, -1.0f, -1.0f, -1.0f);
            float4* orow4 = reinterpret_cast<float4*>(orow_s);
            for (int t2 = (a0 >> 2) + lane; t2 < 256; t2 += 32)
                orow4[t2] = m1;
        }

        if (out_counts) {
#pragma unroll
            for (int d = 16; d > 0; d >>= 1)
                cnt += __shfl_xor_sync(0xffffffffu, cnt, d);
            if (lane == 0) out_counts[row] = (float)cnt;
        }
    } else {
        // ============ FULL PATH: exact 1024 sort (rare; may spill) ============
        float4* orow = reinterpret_cast<float4*>(orow_s);
        u64 key[32];
#pragma unroll
        for (int q = 0; q < 8; ++q) {
            float4 f = rowp4[lane * 8 + q];
            int base = (lane << 5) + (q << 2);
            key[q*4+0] = ((u64)__float_as_uint(f.x) << 32) | (u32)(1023 - (base + 0));
            key[q*4+1] = ((u64)__float_as_uint(f.y) << 32) | (u32)(1023 - (base + 1));
            key[q*4+2] = ((u64)__float_as_uint(f.z) << 32) | (u32)(1023 - (base + 2));
            key[q*4+3] = ((u64)__float_as_uint(f.w) << 32) | (u32)(1023 - (base + 3));
        }

#pragma unroll
        for (int k = 2; k <= 1024; k <<= 1) {
#pragma unroll
            for (int j = k >> 1; j > 0; j >>= 1) {
                if (j >= 32) {
                    const int jl = j >> 5;
                    const bool keepMax =
                        (((lane & (k >> 5)) == 0) == ((lane & jl) == 0));
#pragma unroll
                    for (int r = 0; r < 32; ++r) {
                        u64 mine  = key[r];
                        u64 other = __shfl_xor_sync(0xffffffffu, mine, jl);
                        bool q = (mine > other) == keepMax;
                        key[r] = q ? mine : other;
                    }
                } else {
#pragma unroll
                    for (int r = 0; r < 32; ++r) {
                        if ((r & j) == 0) {
                            bool descBlk = (k >= 32)
                                ? ((lane & (k >> 5)) == 0)
                                : ((r & k) == 0);
                            cas(key[r], key[r | j], descBlk);
                        }
                    }
                }
            }
        }

        float tot = 0.0f;
#pragma unroll
        for (int r = 0; r < 32; ++r)
            tot += __uint_as_float((u32)(key[r] >> 32));
        float sc = tot;
#pragma unroll
        for (int d = 1; d < 32; d <<= 1) {
            float n = __shfl_up_sync(0xffffffffu, sc, d);
            if (lane >= d) sc += n;
        }
        float run = sc - tot;

        int cnt = 0; float ov[4];
#pragma unroll
        for (int r = 0; r < 32; ++r) {
            run += __uint_as_float((u32)(key[r] >> 32));
            bool sel = (run <= thr);
            int id = 1023 - (int)((u32)key[r]);
            ov[r & 3] = sel ? (float)id : -1.0f;
            cnt += sel ? 1 : 0;
            if ((r & 3) == 3)
                orow[lane * 8 + (r >> 2)] = make_float4(ov[0], ov[1], ov[2], ov[3]);
        }

        if (out_counts) {
#pragma unroll
            for (int d = 16; d > 0; d >>= 1)
                cnt += __shfl_xor_sync(0xffffffffu, cnt, d);
            if (lane == 0) out_counts[row] = (float)cnt;
        }
    }
}

extern "C" void kernel_launch(void* const* d_in, const int* in_sizes, int n_in,
                              void* d_out, int out_size)
{
    const float* atn = (const float*)d_in[0];
    const float* thr = (const float*)d_in[1];
    (void)n_in;

    const int S    = 1024;
    const int rows = in_sizes[0] / S;                 // 65536
    long long padded = (long long)rows * S;           // 67,108,864

    float* out    = (float*)d_out;
    float* counts = ((long long)out_size >= padded + rows) ? (out + padded) : nullptr;

    dim3 block(32 * NW);                              // 8 warps = 8 rows per CTA
    dim3 grid(rows / NW);
    topp_kernel<<<grid, block>>>(atn, thr, out, counts);
}